// round 2
// baseline (speedup 1.0000x reference)
#include <cuda_runtime.h>

#define NN 64
#define NB (NN * NN)     // 4096 (s,t) pairs -> 4096 CTAs
#define ITERS 10         // |lambda2| ~ 0.07-0.2 -> error <= 1e-7

// Per-block partial contributions: scratch[b][n]. 4096*64*4 = 1 MB.
__device__ float g_scratch[NB * NN];

// One CTA per (s,t). Thread k owns row k of M = r_const[s,t,:,:] in registers.
// Power iteration: v <- M v, v stays sum-1 because M is column-stochastic.
__global__ __launch_bounds__(NN, 8)
void power_kernel(const float* __restrict__ x,
                  const float* __restrict__ wt,
                  const float* __restrict__ rc)
{
    const int b = blockIdx.x;        // b = s*64 + t
    const int k = threadIdx.x;       // 0..63
    const float* M = rc + (size_t)b * (NN * NN);   // row-major [k][m]

    // Load row k (256 B) as 16 float4s: every byte of the 16 KB tile is used,
    // adjacent threads cover adjacent 256B rows -> full DRAM utilization.
    float4 row[16];
    const float4* rowp = reinterpret_cast<const float4*>(M + k * NN);
#pragma unroll
    for (int i = 0; i < 16; ++i) row[i] = rowp[i];

    __shared__ __align__(16) float v[NN];
    v[k] = 1.0f / NN;
    __syncthreads();

#pragma unroll 1
    for (int it = 0; it < ITERS; ++it) {
        float a0 = 0.f, a1 = 0.f, a2 = 0.f, a3 = 0.f;
#pragma unroll
        for (int i = 0; i < 16; ++i) {
            // LDS.128 broadcast (all threads same address -> conflict-free)
            float4 vv = reinterpret_cast<const float4*>(v)[i];
            a0 = fmaf(row[i].x, vv.x, a0);
            a1 = fmaf(row[i].y, vv.y, a1);
            a2 = fmaf(row[i].z, vv.z, a2);
            a3 = fmaf(row[i].w, vv.w, a3);
        }
        float acc = (a0 + a1) + (a2 + a3);
        __syncthreads();      // everyone done reading old v
        v[k] = acc;
        __syncthreads();      // new v visible
    }

    // Epilogue: coef = x[s,t]*wt[s,t]*r_const[s,t,s,s] / v[s]
    __shared__ float coef;
    if (k == 0) {
        const int s = b >> 6;
        const float rdiag = M[s * NN + s];   // r_const[s,t,s,s]
        const float T = x[b] * wt[b] * rdiag;
        coef = T / v[s];
    }
    __syncthreads();
    g_scratch[b * NN + k] = coef * v[k];
}

// 64 blocks, block n sums scratch[:, n]. Deterministic order.
__global__ __launch_bounds__(256)
void reduce_kernel(float* __restrict__ out)
{
    const int n = blockIdx.x;
    const int tid = threadIdx.x;
    float acc = 0.f;
    for (int b = tid; b < NB; b += 256)
        acc += g_scratch[b * NN + n];

    __shared__ float sm[256];
    sm[tid] = acc;
    __syncthreads();
#pragma unroll
    for (int off = 128; off > 0; off >>= 1) {
        if (tid < off) sm[tid] += sm[tid + off];
        __syncthreads();
    }
    if (tid == 0) out[n] = sm[0];
}

extern "C" void kernel_launch(void* const* d_in, const int* in_sizes, int n_in,
                              void* d_out, int out_size)
{
    // metadata order: x, weights_t, weights_r (unused: r_zeros==0), r_zeros, r_const
    const float* x  = (const float*)d_in[0];
    const float* wt = (const float*)d_in[1];
    const float* rc = (const float*)d_in[4];

    power_kernel<<<NB, NN>>>(x, wt, rc);
    reduce_kernel<<<NN, 256>>>((float*)d_out);
}

// round 3
// speedup vs baseline: 1.2906x; 1.2906x over previous
#include <cuda_runtime.h>

#define NN 64
#define NB (NN * NN)   // 4096 (s,t) pairs -> 4096 CTAs
#define ITERS 7        // |lambda2| ~ 0.065 -> iteration error ~5e-9 << fp32 floor

// Packed f32x2 FMA / ADD (Blackwell): halves FMA instruction count.
__device__ __forceinline__ unsigned long long ffma2(unsigned long long a,
                                                    unsigned long long b,
                                                    unsigned long long c) {
    unsigned long long d;
    asm("fma.rn.f32x2 %0, %1, %2, %3;" : "=l"(d) : "l"(a), "l"(b), "l"(c));
    return d;
}
__device__ __forceinline__ unsigned long long fadd2(unsigned long long a,
                                                    unsigned long long b) {
    unsigned long long d;
    asm("add.rn.f32x2 %0, %1, %2;" : "=l"(d) : "l"(a), "l"(b));
    return d;
}

__global__ void zero_out(float* __restrict__ out) {
    out[threadIdx.x] = 0.0f;
}

// One CTA per (s,t). Thread k owns row k of M = r_const[s,t,:,:] in registers
// (16 x 16B loads, fully coalesced, every byte of the 16KB tile used once).
// Power iteration: v <- M v; M is column-stochastic so sum(v) stays 1.
__global__ __launch_bounds__(NN, 8)
void power_kernel(const float* __restrict__ x,
                  const float* __restrict__ wt,
                  const float* __restrict__ rc,
                  float* __restrict__ out)
{
    const int b = blockIdx.x;       // b = s*64 + t
    const int k = threadIdx.x;      // 0..63
    const float* M = rc + (size_t)b * (NN * NN);

    // Row k as 16 x (2 packed f32x2) = 64 floats in 32 u64 regs.
    ulonglong2 row[16];
    const ulonglong2* rowp = reinterpret_cast<const ulonglong2*>(M + k * NN);
#pragma unroll
    for (int i = 0; i < 16; ++i) row[i] = rowp[i];

    __shared__ __align__(16) float v[NN];
    v[k] = 1.0f / NN;
    __syncthreads();

#pragma unroll 1
    for (int it = 0; it < ITERS; ++it) {
        unsigned long long a0 = 0ull, a1 = 0ull, a2 = 0ull, a3 = 0ull;
#pragma unroll
        for (int i = 0; i < 16; ++i) {
            // LDS.128 broadcast (all lanes same address -> conflict-free)
            ulonglong2 vv = reinterpret_cast<const ulonglong2*>(v)[i];
            if (i & 1) {
                a2 = ffma2(row[i].x, vv.x, a2);
                a3 = ffma2(row[i].y, vv.y, a3);
            } else {
                a0 = ffma2(row[i].x, vv.x, a0);
                a1 = ffma2(row[i].y, vv.y, a1);
            }
        }
        unsigned long long s2 = fadd2(fadd2(a0, a2), fadd2(a1, a3));
        float2 sf = *reinterpret_cast<float2*>(&s2);
        float acc = sf.x + sf.y;

        __syncthreads();          // everyone done reading old v
        v[k] = acc;
        __syncthreads();          // new v visible
    }

    // coef = x[s,t]*wt[s,t]*r_const[s,t,s,s] / v[s]; scale-invariant in v.
    const int s = b >> 6;
    const float coef = x[b] * wt[b] * __ldg(&M[s * NN + s]) / v[s];

    // Fused reduction: spread-address REDG (64 distinct addresses per warp),
    // ~0.25 updates/cyc/address chip-wide -> far below LTS atomic ceiling.
    atomicAdd(&out[k], coef * v[k]);
}

extern "C" void kernel_launch(void* const* d_in, const int* in_sizes, int n_in,
                              void* d_out, int out_size)
{
    // inputs: x, weights_t, weights_r (unused), r_zeros (all-zero), r_const
    const float* x  = (const float*)d_in[0];
    const float* wt = (const float*)d_in[1];
    const float* rc = (const float*)d_in[4];
    float* out = (float*)d_out;

    zero_out<<<1, NN>>>(out);
    power_kernel<<<NB, NN>>>(x, wt, rc, out);
}